// round 3
// baseline (speedup 1.0000x reference)
#include <cuda_runtime.h>
#include <math.h>

#define NN  50000
#define NE  250000
#define NEA 500000
#define NR  300
#define EHD 300
#define THD 100

// ------------------------------------------------------------------
// Static device scratch (no runtime allocation allowed)
// ------------------------------------------------------------------
struct Scratch {
    float X[(size_t)NN * EHD];
    float Y[(size_t)NN * EHD];
    float Z[(size_t)NN * EHD];
    float S[(size_t)NN * THD];
    float dinv[NN];
    float RF[NR * EHD];
    float ER0[NR * EHD];
    float ER1[NR * EHD];
    float ER2[NR * EHD];
    float cR0[NR];
    float cR1[NR];
    float cR2[NR];
    float xa[NN];
    float xj[NN];
    int cnt_all[NN];
    int cnt_h[NN];
    int cnt_t[NN];
    int cnt_r[NR];
    int off_all[NN + 1];
    int off_h[NN + 1];
    int off_t[NN + 1];
    int off_r[NR + 1];
    int cur_all[NN];
    int cur_h[NN];
    int cur_t[NN];
    int cur_r[NR];
    int ord_all[NEA];
    int ord_h[NE];
    int ord_t[NE];
    int ord_r[NE];
};
__device__ Scratch g_scr;

// ------------------------------------------------------------------
// helpers
// ------------------------------------------------------------------
__device__ __forceinline__ float lrelu01(float z) { return z > 0.f ? z : 0.01f * z; }

__device__ __forceinline__ float wredsum(float v) {
    #pragma unroll
    for (int o = 16; o > 0; o >>= 1) v += __shfl_xor_sync(0xffffffffu, v, o);
    return v;
}
__device__ __forceinline__ float wredmax(float v) {
    #pragma unroll
    for (int o = 16; o > 0; o >>= 1) v = fmaxf(v, __shfl_xor_sync(0xffffffffu, v, o));
    return v;
}

static inline int divup(int a, int b) { return (a + b - 1) / b; }

// ------------------------------------------------------------------
// small utility kernels
// ------------------------------------------------------------------
__global__ void k_zero_i(int* __restrict__ p, int n) {
    for (int i = blockIdx.x * blockDim.x + threadIdx.x; i < n; i += gridDim.x * blockDim.x)
        p[i] = 0;
}

__global__ void k_hist(const int* __restrict__ keys, int n, int* __restrict__ cnt) {
    for (int i = blockIdx.x * blockDim.x + threadIdx.x; i < n; i += gridDim.x * blockDim.x)
        atomicAdd(&cnt[keys[i]], 1);
}

__global__ void k_scatter(const int* __restrict__ keys, int n,
                          int* __restrict__ cur, int* __restrict__ ord) {
    for (int i = blockIdx.x * blockDim.x + threadIdx.x; i < n; i += gridDim.x * blockDim.x) {
        int pos = atomicAdd(&cur[keys[i]], 1);
        ord[pos] = i;
    }
}

__global__ void k_dinv(const int* __restrict__ cnt, float* __restrict__ dinv) {
    int i = blockIdx.x * blockDim.x + threadIdx.x;
    if (i < NN) {
        int d = cnt[i];
        dinv[i] = (d > 0) ? rsqrtf((float)d) : 0.0f;
    }
}

// single-block exclusive scan; writes off[0..n] and cur[0..n-1]
__global__ void k_scan(const int* __restrict__ c, int n,
                       int* __restrict__ off, int* __restrict__ cur) {
    __shared__ int sh[1024];
    __shared__ int carry;
    int tid = threadIdx.x;
    if (tid == 0) carry = 0;
    __syncthreads();
    for (int base = 0; base < n; base += 1024) {
        int v = (base + tid < n) ? c[base + tid] : 0;
        sh[tid] = v;
        __syncthreads();
        for (int d = 1; d < 1024; d <<= 1) {
            int t2 = (tid >= d) ? sh[tid - d] : 0;
            __syncthreads();
            sh[tid] += t2;
            __syncthreads();
        }
        int ex = carry + sh[tid] - v;
        if (base + tid < n) { off[base + tid] = ex; cur[base + tid] = ex; }
        __syncthreads();
        if (tid == 0) carry += sh[1023];
        __syncthreads();
    }
    if (tid == 0) off[n] = carry;
}

// ------------------------------------------------------------------
// row dot:  out[r] = M[r,:] . v    (warp per row)
// ------------------------------------------------------------------
__global__ void k_rowdot(const float* __restrict__ Mtx, const float* __restrict__ v,
                         float* __restrict__ out, int rows, int cols) {
    int r = (blockIdx.x * blockDim.x + threadIdx.x) >> 5;
    int lane = threadIdx.x & 31;
    if (r >= rows) return;
    const float* mr = Mtx + (size_t)r * cols;
    float s = 0.f;
    for (int d = lane; d < cols; d += 32) s += mr[d] * v[d];
    s = wredsum(s);
    if (lane == 0) out[r] = s;
}

// ------------------------------------------------------------------
// GCN:  y[n,:] = relu( dinv[n] * sum_{e: i=n} dinv[j_e] * x[j_e,:] )
// warp per node over CSR(i_all)
// ------------------------------------------------------------------
__global__ void k_gcn(const float* __restrict__ xin, float* __restrict__ yout,
                      const int* __restrict__ off, const int* __restrict__ ord,
                      const int* __restrict__ jarr, const float* __restrict__ dinv) {
    int n = (blockIdx.x * blockDim.x + threadIdx.x) >> 5;
    if (n >= NN) return;
    int lane = threadIdx.x & 31;
    int s0 = off[n], s1 = off[n + 1];
    float acc[10];
    #pragma unroll
    for (int k = 0; k < 10; k++) acc[k] = 0.f;
    for (int p = s0; p < s1; p++) {
        int e = ord[p];
        int j = jarr[e];
        float w = dinv[j];
        const float* xr = xin + (size_t)j * EHD;
        #pragma unroll
        for (int k = 0; k < 10; k++) {
            int d = lane + 32 * k;
            if (d < EHD) acc[k] += w * xr[d];
        }
    }
    float dn = dinv[n];
    #pragma unroll
    for (int k = 0; k < 10; k++) {
        int d = lane + 32 * k;
        if (d < EHD) yout[(size_t)n * EHD + d] = fmaxf(dn * acc[k], 0.f);
    }
}

// ------------------------------------------------------------------
// SGEMM: C = A[MxK] @ W[KxN] + bias
//   mode 0: OUT = C
//   mode 1: g = sigmoid(C); OUT = g*Yp + (1-g)*A   (requires N == K)
// BM=128, BN=64, BK=16, 256 threads, 8x4 micro-tile
// ------------------------------------------------------------------
__global__ __launch_bounds__(256) void k_sgemm(
    const float* __restrict__ A, const float* __restrict__ W,
    const float* __restrict__ bias, const float* __restrict__ Yp,
    float* __restrict__ OUT, int M, int N, int K, int mode) {
    const int BM = 128, BN = 64, BK = 16;
    __shared__ float As[16][128];
    __shared__ float Bs[16][64];
    int mb = blockIdx.x * BM, nb = blockIdx.y * BN;
    int tid = threadIdx.x;
    int ty = tid >> 4;   // 0..15 -> rows ty*8..ty*8+7
    int tx = tid & 15;   // 0..15 -> cols tx*4..tx*4+3
    float acc[8][4];
    #pragma unroll
    for (int i = 0; i < 8; i++)
        #pragma unroll
        for (int j = 0; j < 4; j++) acc[i][j] = 0.f;

    for (int k0 = 0; k0 < K; k0 += BK) {
        #pragma unroll
        for (int l = 0; l < 8; l++) {
            int idx = tid + l * 256;
            int ar = idx >> 4;
            int ak = idx & 15;
            int gm = mb + ar, gk = k0 + ak;
            As[ak][ar] = (gm < M && gk < K) ? A[(size_t)gm * K + gk] : 0.f;
        }
        #pragma unroll
        for (int l = 0; l < 4; l++) {
            int idx = tid + l * 256;
            int bn = idx & 63;
            int bk = idx >> 6;
            int gk = k0 + bk, gn = nb + bn;
            Bs[bk][bn] = (gk < K && gn < N) ? W[(size_t)gk * N + gn] : 0.f;
        }
        __syncthreads();
        #pragma unroll
        for (int k = 0; k < BK; k++) {
            float a[8], b[4];
            #pragma unroll
            for (int i = 0; i < 8; i++) a[i] = As[k][ty * 8 + i];
            #pragma unroll
            for (int j = 0; j < 4; j++) b[j] = Bs[k][tx * 4 + j];
            #pragma unroll
            for (int i = 0; i < 8; i++)
                #pragma unroll
                for (int j = 0; j < 4; j++) acc[i][j] += a[i] * b[j];
        }
        __syncthreads();
    }
    #pragma unroll
    for (int i = 0; i < 8; i++) {
        int gm = mb + ty * 8 + i;
        if (gm >= M) continue;
        #pragma unroll
        for (int j = 0; j < 4; j++) {
            int gn = nb + tx * 4 + j;
            if (gn >= N) continue;
            float c = acc[i][j] + bias[gn];
            size_t o = (size_t)gm * N + gn;
            if (mode == 0) {
                OUT[o] = c;
            } else {
                float gg = 1.f / (1.f + expf(-c));
                OUT[o] = gg * Yp[o] + (1.f - gg) * A[(size_t)gm * K + gn];
            }
        }
    }
}

// ------------------------------------------------------------------
// per-relation means + rf2 + RF assembly. One block (256 thr) per relation.
// RF[r] = concat( cat[r] @ sr1_w + sr1_b , mh[r], mt[r] )
// ------------------------------------------------------------------
__global__ __launch_bounds__(256) void k_relmean(
    const float* __restrict__ s, const int* __restrict__ off,
    const int* __restrict__ ordv, const int* __restrict__ harr,
    const int* __restrict__ tarr, const int* __restrict__ cntr,
    const float* __restrict__ sr1w, const float* __restrict__ sr1b,
    float* __restrict__ RF) {
    int r = blockIdx.x;
    int tid = threadIdx.x;
    __shared__ float acc[200];
    __shared__ float cat[200];
    if (tid < 200) acc[tid] = 0.f;
    __syncthreads();

    int wi = tid >> 5, lane = tid & 31;   // 8 warps
    int s0 = off[r], s1 = off[r + 1];
    float lh[4] = {0.f, 0.f, 0.f, 0.f};
    float lt[4] = {0.f, 0.f, 0.f, 0.f};
    for (int p = s0 + wi; p < s1; p += 8) {
        int e = ordv[p];
        const float* sh_ = s + (size_t)harr[e] * THD;
        const float* st_ = s + (size_t)tarr[e] * THD;
        #pragma unroll
        for (int q = 0; q < 4; q++) {
            int d = lane + 32 * q;
            if (d < THD) { lh[q] += sh_[d]; lt[q] += st_[d]; }
        }
    }
    #pragma unroll
    for (int q = 0; q < 4; q++) {
        int d = lane + 32 * q;
        if (d < THD) {
            atomicAdd(&acc[d], lh[q]);
            atomicAdd(&acc[THD + d], lt[q]);
        }
    }
    __syncthreads();
    float c = fmaxf((float)cntr[r], 1.f);
    if (tid < 200) cat[tid] = acc[tid] / c;
    __syncthreads();
    if (tid < 100) {
        float a = sr1b[tid];
        #pragma unroll 4
        for (int k = 0; k < 200; k++) a += cat[k] * sr1w[k * 100 + tid];
        float* rf = RF + (size_t)r * EHD;
        rf[tid]       = a;              // rf2 (== x_type for non-empty relations)
        rf[100 + tid] = cat[tid];       // mh
        rf[200 + tid] = cat[100 + tid]; // mt
    }
}

// ------------------------------------------------------------------
// r2e round: x[n,:] += relu( sum_e softmax_e( lrelu(xa[n]+cR[rel_e]) ) * ER[rel_e,:] )
// warp per node over CSR(idx)
// ------------------------------------------------------------------
__global__ void k_r2e(float* __restrict__ x, const float* __restrict__ xa,
                      const float* __restrict__ ER, const float* __restrict__ cR,
                      const int* __restrict__ off, const int* __restrict__ ordv,
                      const int* __restrict__ rel) {
    int n = (blockIdx.x * blockDim.x + threadIdx.x) >> 5;
    if (n >= NN) return;
    int lane = threadIdx.x & 31;
    int s0 = off[n], s1 = off[n + 1];
    if (s0 == s1) return;
    float xan = xa[n];

    float m = -1e30f;
    for (int p = s0 + lane; p < s1; p += 32)
        m = fmaxf(m, lrelu01(xan + cR[rel[ordv[p]]]));
    m = wredmax(m);

    float den = 0.f;
    for (int p = s0 + lane; p < s1; p += 32)
        den += expf(lrelu01(xan + cR[rel[ordv[p]]]) - m);
    den = wredsum(den);
    float inv = 1.f / den;

    float acc[10];
    #pragma unroll
    for (int k = 0; k < 10; k++) acc[k] = 0.f;
    for (int p = s0; p < s1; p++) {
        int e = ordv[p];
        int r = rel[e];
        float w = expf(lrelu01(xan + cR[r]) - m) * inv;
        const float* er = ER + (size_t)r * EHD;
        #pragma unroll
        for (int k = 0; k < 10; k++) {
            int d = lane + 32 * k;
            if (d < EHD) acc[k] += w * er[d];
        }
    }
    #pragma unroll
    for (int k = 0; k < 10; k++) {
        int d = lane + 32 * k;
        if (d < EHD) x[(size_t)n * EHD + d] += fmaxf(acc[k], 0.f);
    }
}

// ------------------------------------------------------------------
// final GAT + fc output. warp per node over CSR(i_all)
// ------------------------------------------------------------------
__global__ void k_gatfinal(const float* __restrict__ x, const float* __restrict__ xai,
                           const float* __restrict__ xjv, const int* __restrict__ off,
                           const int* __restrict__ ordv, const int* __restrict__ jarr,
                           const float* __restrict__ fcw, const float* __restrict__ fcb,
                           float* __restrict__ outp) {
    int n = (blockIdx.x * blockDim.x + threadIdx.x) >> 5;
    if (n >= NN) return;
    int lane = threadIdx.x & 31;
    int s0 = off[n], s1 = off[n + 1];
    float acc[10];
    #pragma unroll
    for (int k = 0; k < 10; k++) acc[k] = 0.f;

    if (s1 > s0) {
        float xin = xai[n];
        float m = -1e30f;
        for (int p = s0 + lane; p < s1; p += 32)
            m = fmaxf(m, lrelu01(xin + xjv[jarr[ordv[p]]]));
        m = wredmax(m);
        float den = 0.f;
        for (int p = s0 + lane; p < s1; p += 32)
            den += expf(lrelu01(xin + xjv[jarr[ordv[p]]]) - m);
        den = wredsum(den);
        float inv = 1.f / den;
        for (int p = s0; p < s1; p++) {
            int e = ordv[p];
            int j = jarr[e];
            float w = expf(lrelu01(xin + xjv[j]) - m) * inv;
            const float* xr = x + (size_t)j * EHD;
            #pragma unroll
            for (int k = 0; k < 10; k++) {
                int d = lane + 32 * k;
                if (d < EHD) acc[k] += w * xr[d];
            }
        }
    }
    float local = 0.f;
    const float* xn = x + (size_t)n * EHD;
    #pragma unroll
    for (int k = 0; k < 10; k++) {
        int d = lane + 32 * k;
        if (d < EHD) local += xn[d] * fcw[d] + fmaxf(acc[k], 0.f) * fcw[EHD + d];
    }
    local = wredsum(local);
    if (lane == 0) outp[n] = local + fcb[0];
}

// ------------------------------------------------------------------
// launcher
// ------------------------------------------------------------------
extern "C" void kernel_launch(void* const* d_in, const int* in_sizes, int n_in,
                              void* d_out, int out_size) {
    const float* x      = (const float*)d_in[0];
    const int*   ei     = (const int*)d_in[1];
    const int*   rel    = (const int*)d_in[2];
    const int*   eia    = (const int*)d_in[3];
    // d_in[4] = rel_size (identity permutation; unused)
    const float* hw1_w  = (const float*)d_in[5];
    const float* hw1_b  = (const float*)d_in[6];
    const float* hw2_w  = (const float*)d_in[7];
    const float* hw2_b  = (const float*)d_in[8];
    const float* tc1_w  = (const float*)d_in[9];
    const float* tc1_b  = (const float*)d_in[10];
    const float* sr1_w  = (const float*)d_in[11];
    const float* sr1_b  = (const float*)d_in[12];
    // d_in[13] a1_w, d_in[14] a5_w: mathematically dead (constant-per-segment softmax)
    const float* wr_w   = (const float*)d_in[15];
    const float* wr_b   = (const float*)d_in[16];
    const float* wr1_w  = (const float*)d_in[17];
    const float* wr1_b  = (const float*)d_in[18];
    const float* wr2_w  = (const float*)d_in[19];
    const float* wr2_b  = (const float*)d_in[20];
    const float* ah_w   = (const float*)d_in[21];
    const float* ah1_w  = (const float*)d_in[22];
    const float* at_w   = (const float*)d_in[23];
    const float* ar1_w  = (const float*)d_in[24];
    const float* ar2_w  = (const float*)d_in[25];
    const float* ar3_w  = (const float*)d_in[26];
    const float* ai_w   = (const float*)d_in[27];
    const float* aj_w   = (const float*)d_in[28];
    const float* fc_w   = (const float*)d_in[29];
    const float* fc_b   = (const float*)d_in[30];
    float* out = (float*)d_out;

    const int* h  = ei;            // edge_index[0]
    const int* t  = ei + NE;       // edge_index[1]
    const int* jj = eia;           // edge_index_all[0]
    const int* ii = eia + NEA;     // edge_index_all[1]

    Scratch* g = nullptr;
    cudaGetSymbolAddress((void**)&g, g_scr);

    const int TPB = 256;
    const int NODE_BLKS = divup(NN * 32, TPB);

    // ---- counting sorts -------------------------------------------------
    k_zero_i<<<divup(3 * NN + NR, TPB), TPB>>>(g->cnt_all, 3 * NN + NR); // cnt_* contiguous
    k_hist<<<512, TPB>>>(ii, NEA, g->cnt_all);
    k_hist<<<256, TPB>>>(h, NE, g->cnt_h);
    k_hist<<<256, TPB>>>(t, NE, g->cnt_t);
    k_hist<<<256, TPB>>>(rel, NE, g->cnt_r);
    k_scan<<<1, 1024>>>(g->cnt_all, NN, g->off_all, g->cur_all);
    k_scan<<<1, 1024>>>(g->cnt_h, NN, g->off_h, g->cur_h);
    k_scan<<<1, 1024>>>(g->cnt_t, NN, g->off_t, g->cur_t);
    k_scan<<<1, 1024>>>(g->cnt_r, NR, g->off_r, g->cur_r);
    k_dinv<<<divup(NN, TPB), TPB>>>(g->cnt_all, g->dinv);
    k_scatter<<<512, TPB>>>(ii, NEA, g->cur_all, g->ord_all);
    k_scatter<<<256, TPB>>>(h, NE, g->cur_h, g->ord_h);
    k_scatter<<<256, TPB>>>(t, NE, g->cur_t, g->ord_t);
    k_scatter<<<256, TPB>>>(rel, NE, g->cur_r, g->ord_r);

    // ---- highway GCN x2 -------------------------------------------------
    dim3 gemmGrid300(divup(NN, 128), divup(EHD, 64));
    k_gcn<<<NODE_BLKS, TPB>>>(x, g->Y, g->off_all, g->ord_all, jj, g->dinv);
    k_sgemm<<<gemmGrid300, 256>>>(x, hw1_w, hw1_b, g->Y, g->X, NN, EHD, EHD, 1);
    k_gcn<<<NODE_BLKS, TPB>>>(g->X, g->Y, g->off_all, g->ord_all, jj, g->dinv);
    k_sgemm<<<gemmGrid300, 256>>>(g->X, hw2_w, hw2_b, g->Y, g->Z, NN, EHD, EHD, 1);

    // ---- s = Z @ tc1 + b ------------------------------------------------
    dim3 gemmGrid100(divup(NN, 128), divup(THD, 64));
    k_sgemm<<<gemmGrid100, 256>>>(g->Z, tc1_w, tc1_b, nullptr, g->S, NN, THD, EHD, 0);

    // ---- per-relation features RF --------------------------------------
    k_relmean<<<NR, 256>>>(g->S, g->off_r, g->ord_r, h, t, g->cnt_r, sr1_w, sr1_b, g->RF);

    // ---- ER_k = RF @ wr_k + br_k,  cR_k = ER_k . ar_k -------------------
    dim3 gemmGridR(divup(NR, 128), divup(EHD, 64));
    k_sgemm<<<gemmGridR, 256>>>(g->RF, wr_w, wr_b, nullptr, g->ER0, NR, EHD, EHD, 0);
    k_sgemm<<<gemmGridR, 256>>>(g->RF, wr1_w, wr1_b, nullptr, g->ER1, NR, EHD, EHD, 0);
    k_sgemm<<<gemmGridR, 256>>>(g->RF, wr2_w, wr2_b, nullptr, g->ER2, NR, EHD, EHD, 0);
    k_rowdot<<<divup(NR * 32, TPB), TPB>>>(g->ER0, ar1_w, g->cR0, NR, EHD);
    k_rowdot<<<divup(NR * 32, TPB), TPB>>>(g->ER1, ar2_w, g->cR1, NR, EHD);
    k_rowdot<<<divup(NR * 32, TPB), TPB>>>(g->ER2, ar3_w, g->cR2, NR, EHD);

    // ---- three r2e attention rounds (h, t, h) ---------------------------
    k_rowdot<<<NODE_BLKS, TPB>>>(g->Z, ah_w, g->xa, NN, EHD);
    k_r2e<<<NODE_BLKS, TPB>>>(g->Z, g->xa, g->ER0, g->cR0, g->off_h, g->ord_h, rel);
    k_rowdot<<<NODE_BLKS, TPB>>>(g->Z, at_w, g->xa, NN, EHD);
    k_r2e<<<NODE_BLKS, TPB>>>(g->Z, g->xa, g->ER1, g->cR1, g->off_t, g->ord_t, rel);
    k_rowdot<<<NODE_BLKS, TPB>>>(g->Z, ah1_w, g->xa, NN, EHD);
    k_r2e<<<NODE_BLKS, TPB>>>(g->Z, g->xa, g->ER2, g->cR2, g->off_h, g->ord_h, rel);

    // ---- final GAT over edge_index_all + fc -----------------------------
    k_rowdot<<<NODE_BLKS, TPB>>>(g->Z, ai_w, g->xa, NN, EHD);
    k_rowdot<<<NODE_BLKS, TPB>>>(g->Z, aj_w, g->xj, NN, EHD);
    k_gatfinal<<<NODE_BLKS, TPB>>>(g->Z, g->xa, g->xj, g->off_all, g->ord_all, jj,
                                   fc_w, fc_b, out);
    (void)in_sizes; (void)n_in; (void)out_size;
}

// round 5
// speedup vs baseline: 1.3193x; 1.3193x over previous
#include <cuda_runtime.h>
#include <cuda_bf16.h>
#include <stdint.h>
#include <math.h>

#define NN  50000
#define NE  250000
#define NEA 500000
#define NR  300
#define EHD 300
#define THD 100

// ------------------------------------------------------------------
// Static device scratch (no runtime allocation allowed)
// ------------------------------------------------------------------
struct Scratch {
    float X[(size_t)NN * EHD];
    float Y[(size_t)NN * EHD];
    float Z[(size_t)NN * EHD];
    float S[(size_t)NN * THD];
    float dinv[NN];
    float RF[NR * EHD];
    float ER0[NR * EHD];
    float ER1[NR * EHD];
    float ER2[NR * EHD];
    float cR0[NR];
    float cR1[NR];
    float cR2[NR];
    float xa[NN];
    float xj[NN];
    int cnt_all[NN];
    int cnt_h[NN];
    int cnt_t[NN];
    int cnt_r[NR];
    int off_all[NN + 1];
    int off_h[NN + 1];
    int off_t[NN + 1];
    int off_r[NR + 1];
    int cur_all[NN];
    int cur_h[NN];
    int cur_t[NN];
    int cur_r[NR];
    int ord_all[NEA];
    int ord_h[NE];
    int ord_t[NE];
    int ord_r[NE];
    int bsum[64];
    int boff[65];
};
__device__ Scratch g_scr;

// ------------------------------------------------------------------
// helpers
// ------------------------------------------------------------------
__device__ __forceinline__ float lrelu01(float z) { return z > 0.f ? z : 0.01f * z; }

__device__ __forceinline__ float wredsum(float v) {
    #pragma unroll
    for (int o = 16; o > 0; o >>= 1) v += __shfl_xor_sync(0xffffffffu, v, o);
    return v;
}
__device__ __forceinline__ float wredmax(float v) {
    #pragma unroll
    for (int o = 16; o > 0; o >>= 1) v = fmaxf(v, __shfl_xor_sync(0xffffffffu, v, o));
    return v;
}

static inline int divup(int a, int b) { return (a + b - 1) / b; }

// ------------------------------------------------------------------
// small utility kernels
// ------------------------------------------------------------------
__global__ void k_zero_i(int* __restrict__ p, int n) {
    for (int i = blockIdx.x * blockDim.x + threadIdx.x; i < n; i += gridDim.x * blockDim.x)
        p[i] = 0;
}

__global__ void k_hist(const int* __restrict__ keys, int n, int* __restrict__ cnt) {
    for (int i = blockIdx.x * blockDim.x + threadIdx.x; i < n; i += gridDim.x * blockDim.x)
        atomicAdd(&cnt[keys[i]], 1);
}

__global__ void k_scatter(const int* __restrict__ keys, int n,
                          int* __restrict__ cur, int* __restrict__ ord) {
    for (int i = blockIdx.x * blockDim.x + threadIdx.x; i < n; i += gridDim.x * blockDim.x) {
        int pos = atomicAdd(&cur[keys[i]], 1);
        ord[pos] = i;
    }
}

__global__ void k_dinv(const int* __restrict__ cnt, float* __restrict__ dinv) {
    int i = blockIdx.x * blockDim.x + threadIdx.x;
    if (i < NN) {
        int d = cnt[i];
        dinv[i] = (d > 0) ? rsqrtf((float)d) : 0.0f;
    }
}

// ---- 3-phase multi-block exclusive scan ----
__global__ void k_scan_blk(const int* __restrict__ c, int n,
                           int* __restrict__ off, int* __restrict__ bsum) {
    __shared__ int sh[1024];
    int tid = threadIdx.x;
    int idx = blockIdx.x * 1024 + tid;
    int v = (idx < n) ? c[idx] : 0;
    sh[tid] = v;
    __syncthreads();
    #pragma unroll
    for (int d = 1; d < 1024; d <<= 1) {
        int t2 = (tid >= d) ? sh[tid - d] : 0;
        __syncthreads();
        sh[tid] += t2;
        __syncthreads();
    }
    if (idx < n) off[idx] = sh[tid] - v;   // exclusive within block
    if (tid == 1023) bsum[blockIdx.x] = sh[1023];
}

__global__ void k_scan_top(const int* __restrict__ bsum, int nb, int* __restrict__ boff) {
    if (threadIdx.x == 0) {
        int run = 0;
        for (int i = 0; i < nb; i++) { boff[i] = run; run += bsum[i]; }
        boff[nb] = run;
    }
}

__global__ void k_scan_fix(int* __restrict__ off, const int* __restrict__ boff,
                           int n, int* __restrict__ cur) {
    int idx = blockIdx.x * 1024 + threadIdx.x;
    if (idx < n) {
        int v = off[idx] + boff[blockIdx.x];
        off[idx] = v;
        cur[idx] = v;
    }
    if (idx == 0) off[n] = boff[gridDim.x];
}

// ------------------------------------------------------------------
// row dot:  out[r] = M[r,:] . v    (warp per row)
// ------------------------------------------------------------------
__global__ void k_rowdot(const float* __restrict__ Mtx, const float* __restrict__ v,
                         float* __restrict__ out, int rows, int cols) {
    int r = (blockIdx.x * blockDim.x + threadIdx.x) >> 5;
    int lane = threadIdx.x & 31;
    if (r >= rows) return;
    const float* mr = Mtx + (size_t)r * cols;
    float s = 0.f;
    for (int d = lane; d < cols; d += 32) s += mr[d] * v[d];
    s = wredsum(s);
    if (lane == 0) out[r] = s;
}

// ------------------------------------------------------------------
// GCN:  y[n,:] = relu( dinv[n] * sum_{e: i=n} dinv[j_e] * x[j_e,:] )
// ------------------------------------------------------------------
__global__ void k_gcn(const float* __restrict__ xin, float* __restrict__ yout,
                      const int* __restrict__ off, const int* __restrict__ ord,
                      const int* __restrict__ jarr, const float* __restrict__ dinv) {
    int n = (blockIdx.x * blockDim.x + threadIdx.x) >> 5;
    if (n >= NN) return;
    int lane = threadIdx.x & 31;
    int s0 = off[n], s1 = off[n + 1];
    float acc[10];
    #pragma unroll
    for (int k = 0; k < 10; k++) acc[k] = 0.f;
    for (int p = s0; p < s1; p++) {
        int e = ord[p];
        int j = jarr[e];
        float w = dinv[j];
        const float* xr = xin + (size_t)j * EHD;
        #pragma unroll
        for (int k = 0; k < 10; k++) {
            int d = lane + 32 * k;
            if (d < EHD) acc[k] += w * xr[d];
        }
    }
    float dn = dinv[n];
    #pragma unroll
    for (int k = 0; k < 10; k++) {
        int d = lane + 32 * k;
        if (d < EHD) yout[(size_t)n * EHD + d] = fmaxf(dn * acc[k], 0.f);
    }
}

// ------------------------------------------------------------------
// fp32 SGEMM (kept for the tiny 300x300x300 relation GEMMs)
// ------------------------------------------------------------------
__global__ __launch_bounds__(256) void k_sgemm(
    const float* __restrict__ A, const float* __restrict__ W,
    const float* __restrict__ bias, const float* __restrict__ Yp,
    float* __restrict__ OUT, int M, int N, int K, int mode) {
    const int BM = 128, BN = 64, BK = 16;
    __shared__ float As[16][128];
    __shared__ float Bs[16][64];
    int mb = blockIdx.x * BM, nb = blockIdx.y * BN;
    int tid = threadIdx.x;
    int ty = tid >> 4;
    int tx = tid & 15;
    float acc[8][4];
    #pragma unroll
    for (int i = 0; i < 8; i++)
        #pragma unroll
        for (int j = 0; j < 4; j++) acc[i][j] = 0.f;

    for (int k0 = 0; k0 < K; k0 += BK) {
        #pragma unroll
        for (int l = 0; l < 8; l++) {
            int idx = tid + l * 256;
            int ar = idx >> 4;
            int ak = idx & 15;
            int gm = mb + ar, gk = k0 + ak;
            As[ak][ar] = (gm < M && gk < K) ? A[(size_t)gm * K + gk] : 0.f;
        }
        #pragma unroll
        for (int l = 0; l < 4; l++) {
            int idx = tid + l * 256;
            int bn = idx & 63;
            int bk = idx >> 6;
            int gk = k0 + bk, gn = nb + bn;
            Bs[bk][bn] = (gk < K && gn < N) ? W[(size_t)gk * N + gn] : 0.f;
        }
        __syncthreads();
        #pragma unroll
        for (int k = 0; k < BK; k++) {
            float a[8], b[4];
            #pragma unroll
            for (int i = 0; i < 8; i++) a[i] = As[k][ty * 8 + i];
            #pragma unroll
            for (int j = 0; j < 4; j++) b[j] = Bs[k][tx * 4 + j];
            #pragma unroll
            for (int i = 0; i < 8; i++)
                #pragma unroll
                for (int j = 0; j < 4; j++) acc[i][j] += a[i] * b[j];
        }
        __syncthreads();
    }
    #pragma unroll
    for (int i = 0; i < 8; i++) {
        int gm = mb + ty * 8 + i;
        if (gm >= M) continue;
        #pragma unroll
        for (int j = 0; j < 4; j++) {
            int gn = nb + tx * 4 + j;
            if (gn >= N) continue;
            float c = acc[i][j] + bias[gn];
            size_t o = (size_t)gm * N + gn;
            if (mode == 0) {
                OUT[o] = c;
            } else {
                float gg = 1.f / (1.f + expf(-c));
                OUT[o] = gg * Yp[o] + (1.f - gg) * A[(size_t)gm * K + gn];
            }
        }
    }
}

// ------------------------------------------------------------------
// bf16-split tensor-core GEMM:  C = A @ W + bias   (A,W,C fp32 in gmem)
// a = a_hi + a_lo (bf16 each); C = Ahi*Whi + Ahi*Wlo + Alo*Whi
// BM=128, BN=64, BK=16, 256 threads, 8 warps, warp-tile 32x32
// mode 0: OUT = C; mode 1: highway (g=sigmoid(C); OUT=g*Yp+(1-g)*A), N==K
// ------------------------------------------------------------------
#define MMA_BF16(c, a, b) \
    asm volatile("mma.sync.aligned.m16n8k16.row.col.f32.bf16.bf16.f32 " \
        "{%0,%1,%2,%3}, {%4,%5,%6,%7}, {%8,%9}, {%0,%1,%2,%3};" \
        : "+f"((c)[0]), "+f"((c)[1]), "+f"((c)[2]), "+f"((c)[3]) \
        : "r"((a)[0]), "r"((a)[1]), "r"((a)[2]), "r"((a)[3]), \
          "r"((b)[0]), "r"((b)[1]))

#define LDSM_X4(r, p) \
    asm volatile("ldmatrix.sync.aligned.m8n8.x4.shared.b16 {%0,%1,%2,%3}, [%4];" \
        : "=r"((r)[0]), "=r"((r)[1]), "=r"((r)[2]), "=r"((r)[3]) : "r"(p))

#define LDSM_X2T(r, p) \
    asm volatile("ldmatrix.sync.aligned.m8n8.x2.trans.shared.b16 {%0,%1}, [%2];" \
        : "=r"((r)[0]), "=r"((r)[1]) : "r"(p))

#define AST 24
#define BST 72

__global__ __launch_bounds__(256) void k_hgemm(
    const float* __restrict__ A, const float* __restrict__ W,
    const float* __restrict__ bias, const float* __restrict__ Yp,
    float* __restrict__ OUT, int M, int N, int K, int mode) {
    __shared__ __nv_bfloat16 sAh[128 * AST];
    __shared__ __nv_bfloat16 sAl[128 * AST];
    __shared__ __nv_bfloat16 sBh[16 * BST];
    __shared__ __nv_bfloat16 sBl[16 * BST];

    const int mb = blockIdx.x * 128, nb = blockIdx.y * 64;
    const int tid = threadIdx.x;
    const int lane = tid & 31;
    const int wid = tid >> 5;
    const int warp_m = (wid & 3) * 32;   // 0,32,64,96
    const int warp_n = (wid >> 2) * 32;  // 0,32

    float acc[2][4][4];
    #pragma unroll
    for (int mt = 0; mt < 2; mt++)
        #pragma unroll
        for (int nt = 0; nt < 4; nt++)
            #pragma unroll
            for (int q = 0; q < 4; q++) acc[mt][nt][q] = 0.f;

    // ldmatrix lane address offsets (element indices into smem tiles)
    const int a_sub = lane >> 3;                    // 0..3
    const int a_r   = lane & 7;
    const int a_row_off = ((a_sub & 1) << 3) + a_r; // +0/+8 within 16-row tile
    const int a_col     = (a_sub >> 1) << 3;        // 0 or 8
    uint32_t pAh[2], pAl[2];
    #pragma unroll
    for (int mt = 0; mt < 2; mt++) {
        int row = warp_m + mt * 16 + a_row_off;
        pAh[mt] = (uint32_t)__cvta_generic_to_shared(&sAh[row * AST + a_col]);
        pAl[mt] = (uint32_t)__cvta_generic_to_shared(&sAl[row * AST + a_col]);
    }
    const int b_row = lane & 15;
    uint32_t pBh[4], pBl[4];
    #pragma unroll
    for (int nt = 0; nt < 4; nt++) {
        int col = warp_n + nt * 8;
        pBh[nt] = (uint32_t)__cvta_generic_to_shared(&sBh[b_row * BST + col]);
        pBl[nt] = (uint32_t)__cvta_generic_to_shared(&sBl[b_row * BST + col]);
    }

    // global load assignments
    const int la_row = tid >> 1;           // 0..127
    const int la_cb  = (tid & 1) * 8;      // 0 or 8
    const int lb_row = tid >> 4;           // 0..15
    const int lb_cb  = (tid & 15) * 4;     // 0..60

    for (int k0 = 0; k0 < K; k0 += 16) {
        __syncthreads();
        // load + convert A tile [128 x 16]
        {
            int gm = mb + la_row;
            const float* ar = A + (size_t)gm * K;
            #pragma unroll
            for (int q = 0; q < 8; q++) {
                int c = la_cb + q;
                int gk = k0 + c;
                float v = (gm < M && gk < K) ? __ldg(&ar[gk]) : 0.f;
                __nv_bfloat16 hi = __float2bfloat16(v);
                float lo = v - __bfloat162float(hi);
                sAh[la_row * AST + c] = hi;
                sAl[la_row * AST + c] = __float2bfloat16(lo);
            }
        }
        // load + convert B tile [16 x 64]
        {
            int gk = k0 + lb_row;
            const float* wr = W + (size_t)gk * N;
            #pragma unroll
            for (int q = 0; q < 4; q++) {
                int c = lb_cb + q;
                int gn = nb + c;
                float v = (gk < K && gn < N) ? __ldg(&wr[gn]) : 0.f;
                __nv_bfloat16 hi = __float2bfloat16(v);
                float lo = v - __bfloat162float(hi);
                sBh[lb_row * BST + c] = hi;
                sBl[lb_row * BST + c] = __float2bfloat16(lo);
            }
        }
        __syncthreads();

        uint32_t ah[2][4], al[2][4], bh[4][2], bl[4][2];
        #pragma unroll
        for (int mt = 0; mt < 2; mt++) { LDSM_X4(ah[mt], pAh[mt]); LDSM_X4(al[mt], pAl[mt]); }
        #pragma unroll
        for (int nt = 0; nt < 4; nt++) { LDSM_X2T(bh[nt], pBh[nt]); LDSM_X2T(bl[nt], pBl[nt]); }

        #pragma unroll
        for (int mt = 0; mt < 2; mt++)
            #pragma unroll
            for (int nt = 0; nt < 4; nt++) {
                MMA_BF16(acc[mt][nt], ah[mt], bh[nt]);
                MMA_BF16(acc[mt][nt], ah[mt], bl[nt]);
                MMA_BF16(acc[mt][nt], al[mt], bh[nt]);
            }
    }

    // epilogue
    const int erow = lane >> 2;
    const int ecol = (lane & 3) * 2;
    #pragma unroll
    for (int mt = 0; mt < 2; mt++) {
        #pragma unroll
        for (int nt = 0; nt < 4; nt++) {
            int r0 = mb + warp_m + mt * 16 + erow;
            int c0 = nb + warp_n + nt * 8 + ecol;
            #pragma unroll
            for (int q = 0; q < 4; q++) {
                int gm = r0 + (q >> 1) * 8;
                int gn = c0 + (q & 1);
                if (gm >= M || gn >= N) continue;
                float c = acc[mt][nt][q] + bias[gn];
                size_t o = (size_t)gm * N + gn;
                if (mode == 0) {
                    OUT[o] = c;
                } else {
                    float gg = 1.f / (1.f + expf(-c));
                    OUT[o] = gg * Yp[o] + (1.f - gg) * A[(size_t)gm * K + gn];
                }
            }
        }
    }
}

// ------------------------------------------------------------------
// per-relation means + rf2 + RF assembly. One block (256 thr) per relation.
// ------------------------------------------------------------------
__global__ __launch_bounds__(256) void k_relmean(
    const float* __restrict__ s, const int* __restrict__ off,
    const int* __restrict__ ordv, const int* __restrict__ harr,
    const int* __restrict__ tarr, const int* __restrict__ cntr,
    const float* __restrict__ sr1w, const float* __restrict__ sr1b,
    float* __restrict__ RF) {
    int r = blockIdx.x;
    int tid = threadIdx.x;
    __shared__ float acc[200];
    __shared__ float cat[200];
    if (tid < 200) acc[tid] = 0.f;
    __syncthreads();

    int wi = tid >> 5, lane = tid & 31;
    int s0 = off[r], s1 = off[r + 1];
    float lh[4] = {0.f, 0.f, 0.f, 0.f};
    float lt[4] = {0.f, 0.f, 0.f, 0.f};
    for (int p = s0 + wi; p < s1; p += 8) {
        int e = ordv[p];
        const float* sh_ = s + (size_t)harr[e] * THD;
        const float* st_ = s + (size_t)tarr[e] * THD;
        #pragma unroll
        for (int q = 0; q < 4; q++) {
            int d = lane + 32 * q;
            if (d < THD) { lh[q] += sh_[d]; lt[q] += st_[d]; }
        }
    }
    #pragma unroll
    for (int q = 0; q < 4; q++) {
        int d = lane + 32 * q;
        if (d < THD) {
            atomicAdd(&acc[d], lh[q]);
            atomicAdd(&acc[THD + d], lt[q]);
        }
    }
    __syncthreads();
    float c = fmaxf((float)cntr[r], 1.f);
    if (tid < 200) cat[tid] = acc[tid] / c;
    __syncthreads();
    if (tid < 100) {
        float a = sr1b[tid];
        #pragma unroll 4
        for (int k = 0; k < 200; k++) a += cat[k] * sr1w[k * 100 + tid];
        float* rf = RF + (size_t)r * EHD;
        rf[tid]       = a;
        rf[100 + tid] = cat[tid];
        rf[200 + tid] = cat[100 + tid];
    }
}

// ------------------------------------------------------------------
// r2e round
// ------------------------------------------------------------------
__global__ void k_r2e(float* __restrict__ x, const float* __restrict__ xa,
                      const float* __restrict__ ER, const float* __restrict__ cR,
                      const int* __restrict__ off, const int* __restrict__ ordv,
                      const int* __restrict__ rel) {
    int n = (blockIdx.x * blockDim.x + threadIdx.x) >> 5;
    if (n >= NN) return;
    int lane = threadIdx.x & 31;
    int s0 = off[n], s1 = off[n + 1];
    if (s0 == s1) return;
    float xan = xa[n];

    float m = -1e30f;
    for (int p = s0 + lane; p < s1; p += 32)
        m = fmaxf(m, lrelu01(xan + cR[rel[ordv[p]]]));
    m = wredmax(m);

    float den = 0.f;
    for (int p = s0 + lane; p < s1; p += 32)
        den += expf(lrelu01(xan + cR[rel[ordv[p]]]) - m);
    den = wredsum(den);
    float inv = 1.f / den;

    float acc[10];
    #pragma unroll
    for (int k = 0; k < 10; k++) acc[k] = 0.f;
    for (int p = s0; p < s1; p++) {
        int e = ordv[p];
        int r = rel[e];
        float w = expf(lrelu01(xan + cR[r]) - m) * inv;
        const float* er = ER + (size_t)r * EHD;
        #pragma unroll
        for (int k = 0; k < 10; k++) {
            int d = lane + 32 * k;
            if (d < EHD) acc[k] += w * er[d];
        }
    }
    #pragma unroll
    for (int k = 0; k < 10; k++) {
        int d = lane + 32 * k;
        if (d < EHD) x[(size_t)n * EHD + d] += fmaxf(acc[k], 0.f);
    }
}

// ------------------------------------------------------------------
// final GAT + fc output
// ------------------------------------------------------------------
__global__ void k_gatfinal(const float* __restrict__ x, const float* __restrict__ xai,
                           const float* __restrict__ xjv, const int* __restrict__ off,
                           const int* __restrict__ ordv, const int* __restrict__ jarr,
                           const float* __restrict__ fcw, const float* __restrict__ fcb,
                           float* __restrict__ outp) {
    int n = (blockIdx.x * blockDim.x + threadIdx.x) >> 5;
    if (n >= NN) return;
    int lane = threadIdx.x & 31;
    int s0 = off[n], s1 = off[n + 1];
    float acc[10];
    #pragma unroll
    for (int k = 0; k < 10; k++) acc[k] = 0.f;

    if (s1 > s0) {
        float xin = xai[n];
        float m = -1e30f;
        for (int p = s0 + lane; p < s1; p += 32)
            m = fmaxf(m, lrelu01(xin + xjv[jarr[ordv[p]]]));
        m = wredmax(m);
        float den = 0.f;
        for (int p = s0 + lane; p < s1; p += 32)
            den += expf(lrelu01(xin + xjv[jarr[ordv[p]]]) - m);
        den = wredsum(den);
        float inv = 1.f / den;
        for (int p = s0; p < s1; p++) {
            int e = ordv[p];
            int j = jarr[e];
            float w = expf(lrelu01(xin + xjv[j]) - m) * inv;
            const float* xr = x + (size_t)j * EHD;
            #pragma unroll
            for (int k = 0; k < 10; k++) {
                int d = lane + 32 * k;
                if (d < EHD) acc[k] += w * xr[d];
            }
        }
    }
    float local = 0.f;
    const float* xn = x + (size_t)n * EHD;
    #pragma unroll
    for (int k = 0; k < 10; k++) {
        int d = lane + 32 * k;
        if (d < EHD) local += xn[d] * fcw[d] + fmaxf(acc[k], 0.f) * fcw[EHD + d];
    }
    local = wredsum(local);
    if (lane == 0) outp[n] = local + fcb[0];
}

// ------------------------------------------------------------------
// launcher
// ------------------------------------------------------------------
static void run_scan(const int* cnt, int n, int* off, int* cur, Scratch* g) {
    int nb = divup(n, 1024);
    k_scan_blk<<<nb, 1024>>>(cnt, n, off, g->bsum);
    k_scan_top<<<1, 32>>>(g->bsum, nb, g->boff);
    k_scan_fix<<<nb, 1024>>>(off, g->boff, n, cur);
}

extern "C" void kernel_launch(void* const* d_in, const int* in_sizes, int n_in,
                              void* d_out, int out_size) {
    const float* x      = (const float*)d_in[0];
    const int*   ei     = (const int*)d_in[1];
    const int*   rel    = (const int*)d_in[2];
    const int*   eia    = (const int*)d_in[3];
    const float* hw1_w  = (const float*)d_in[5];
    const float* hw1_b  = (const float*)d_in[6];
    const float* hw2_w  = (const float*)d_in[7];
    const float* hw2_b  = (const float*)d_in[8];
    const float* tc1_w  = (const float*)d_in[9];
    const float* tc1_b  = (const float*)d_in[10];
    const float* sr1_w  = (const float*)d_in[11];
    const float* sr1_b  = (const float*)d_in[12];
    const float* wr_w   = (const float*)d_in[15];
    const float* wr_b   = (const float*)d_in[16];
    const float* wr1_w  = (const float*)d_in[17];
    const float* wr1_b  = (const float*)d_in[18];
    const float* wr2_w  = (const float*)d_in[19];
    const float* wr2_b  = (const float*)d_in[20];
    const float* ah_w   = (const float*)d_in[21];
    const float* ah1_w  = (const float*)d_in[22];
    const float* at_w   = (const float*)d_in[23];
    const float* ar1_w  = (const float*)d_in[24];
    const float* ar2_w  = (const float*)d_in[25];
    const float* ar3_w  = (const float*)d_in[26];
    const float* ai_w   = (const float*)d_in[27];
    const float* aj_w   = (const float*)d_in[28];
    const float* fc_w   = (const float*)d_in[29];
    const float* fc_b   = (const float*)d_in[30];
    float* out = (float*)d_out;

    const int* h  = ei;
    const int* t  = ei + NE;
    const int* jj = eia;
    const int* ii = eia + NEA;

    Scratch* g = nullptr;
    cudaGetSymbolAddress((void**)&g, g_scr);

    const int TPB = 256;
    const int NODE_BLKS = divup(NN * 32, TPB);

    // ---- counting sorts -------------------------------------------------
    k_zero_i<<<divup(3 * NN + NR, TPB), TPB>>>(g->cnt_all, 3 * NN + NR);
    k_hist<<<512, TPB>>>(ii, NEA, g->cnt_all);
    k_hist<<<256, TPB>>>(h, NE, g->cnt_h);
    k_hist<<<256, TPB>>>(t, NE, g->cnt_t);
    k_hist<<<256, TPB>>>(rel, NE, g->cnt_r);
    run_scan(g->cnt_all, NN, g->off_all, g->cur_all, g);
    run_scan(g->cnt_h, NN, g->off_h, g->cur_h, g);
    run_scan(g->cnt_t, NN, g->off_t, g->cur_t, g);
    run_scan(g->cnt_r, NR, g->off_r, g->cur_r, g);
    k_dinv<<<divup(NN, TPB), TPB>>>(g->cnt_all, g->dinv);
    k_scatter<<<512, TPB>>>(ii, NEA, g->cur_all, g->ord_all);
    k_scatter<<<256, TPB>>>(h, NE, g->cur_h, g->ord_h);
    k_scatter<<<256, TPB>>>(t, NE, g->cur_t, g->ord_t);
    k_scatter<<<256, TPB>>>(rel, NE, g->cur_r, g->ord_r);

    // ---- highway GCN x2 (tensor-core bf16-split GEMMs) -------------------
    dim3 gemmGrid300(divup(NN, 128), divup(EHD, 64));
    k_gcn<<<NODE_BLKS, TPB>>>(x, g->Y, g->off_all, g->ord_all, jj, g->dinv);
    k_hgemm<<<gemmGrid300, 256>>>(x, hw1_w, hw1_b, g->Y, g->X, NN, EHD, EHD, 1);
    k_gcn<<<NODE_BLKS, TPB>>>(g->X, g->Y, g->off_all, g->ord_all, jj, g->dinv);
    k_hgemm<<<gemmGrid300, 256>>>(g->X, hw2_w, hw2_b, g->Y, g->Z, NN, EHD, EHD, 1);

    // ---- s = Z @ tc1 + b ------------------------------------------------
    dim3 gemmGrid100(divup(NN, 128), divup(THD, 64));
    k_hgemm<<<gemmGrid100, 256>>>(g->Z, tc1_w, tc1_b, nullptr, g->S, NN, THD, EHD, 0);

    // ---- per-relation features RF ---------------------------------------
    k_relmean<<<NR, 256>>>(g->S, g->off_r, g->ord_r, h, t, g->cnt_r, sr1_w, sr1_b, g->RF);

    // ---- ER_k = RF @ wr_k + br_k (tiny, fp32 path), cR_k = ER_k . ar_k --
    dim3 gemmGridR(divup(NR, 128), divup(EHD, 64));
    k_sgemm<<<gemmGridR, 256>>>(g->RF, wr_w, wr_b, nullptr, g->ER0, NR, EHD, EHD, 0);
    k_sgemm<<<gemmGridR, 256>>>(g->RF, wr1_w, wr1_b, nullptr, g->ER1, NR, EHD, EHD, 0);
    k_sgemm<<<gemmGridR, 256>>>(g->RF, wr2_w, wr2_b, nullptr, g->ER2, NR, EHD, EHD, 0);
    k_rowdot<<<divup(NR * 32, TPB), TPB>>>(g->ER0, ar1_w, g->cR0, NR, EHD);
    k_rowdot<<<divup(NR * 32, TPB), TPB>>>(g->ER1, ar2_w, g->cR1, NR, EHD);
    k_rowdot<<<divup(NR * 32, TPB), TPB>>>(g->ER2, ar3_w, g->cR2, NR, EHD);

    // ---- three r2e attention rounds (h, t, h) ----------------------------
    k_rowdot<<<NODE_BLKS, TPB>>>(g->Z, ah_w, g->xa, NN, EHD);
    k_r2e<<<NODE_BLKS, TPB>>>(g->Z, g->xa, g->ER0, g->cR0, g->off_h, g->ord_h, rel);
    k_rowdot<<<NODE_BLKS, TPB>>>(g->Z, at_w, g->xa, NN, EHD);
    k_r2e<<<NODE_BLKS, TPB>>>(g->Z, g->xa, g->ER1, g->cR1, g->off_t, g->ord_t, rel);
    k_rowdot<<<NODE_BLKS, TPB>>>(g->Z, ah1_w, g->xa, NN, EHD);
    k_r2e<<<NODE_BLKS, TPB>>>(g->Z, g->xa, g->ER2, g->cR2, g->off_h, g->ord_h, rel);

    // ---- final GAT over edge_index_all + fc ------------------------------
    k_rowdot<<<NODE_BLKS, TPB>>>(g->Z, ai_w, g->xa, NN, EHD);
    k_rowdot<<<NODE_BLKS, TPB>>>(g->Z, aj_w, g->xj, NN, EHD);
    k_gatfinal<<<NODE_BLKS, TPB>>>(g->Z, g->xa, g->xj, g->off_all, g->ord_all, jj,
                                   fc_w, fc_b, out);
    (void)in_sizes; (void)n_in; (void)out_size;
}

// round 6
// speedup vs baseline: 1.8092x; 1.3713x over previous
#include <cuda_runtime.h>
#include <cuda_bf16.h>
#include <stdint.h>
#include <math.h>

#define NN  50000
#define NE  250000
#define NEA 500000
#define NR  300
#define EHD 300
#define THD 100

// ------------------------------------------------------------------
// Static device scratch
// ------------------------------------------------------------------
struct Scratch {
    float X[(size_t)NN * EHD];
    float Y[(size_t)NN * EHD];
    float Z[(size_t)NN * EHD];
    float S[(size_t)NN * THD];
    float dinv[NN];
    float RF[NR * EHD];
    float ER0[NR * EHD];
    float ER1[NR * EHD];
    float ER2[NR * EHD];
    float cR0[NR];
    float cR1[NR];
    float cR2[NR];
    float xa[NN];
    float xj[NN];
    float wj[NEA];          // dinv[j] sorted by i_all
    int jall[NEA];          // j sorted by i_all
    int relh[NE];           // rel sorted by h
    int relt[NE];           // rel sorted by t
    int hr[NE];             // h sorted by rel
    int tr[NE];             // t sorted by rel
    int cnt_all[NN];
    int cnt_h[NN];
    int cnt_t[NN];
    int cnt_r[NR];
    int off_all[NN + 1];
    int off_h[NN + 1];
    int off_t[NN + 1];
    int off_r[NR + 1];
    int cur_all[NN];
    int cur_h[NN];
    int cur_t[NN];
    int cur_r[NR];
    int bsum[4][64];
    int boff[4][65];
};
__device__ Scratch g_scr;

// ------------------------------------------------------------------
// helpers
// ------------------------------------------------------------------
__device__ __forceinline__ float lrelu01(float z) { return z > 0.f ? z : 0.01f * z; }

__device__ __forceinline__ float wredsum(float v) {
    #pragma unroll
    for (int o = 16; o > 0; o >>= 1) v += __shfl_xor_sync(0xffffffffu, v, o);
    return v;
}
__device__ __forceinline__ float wredmax(float v) {
    #pragma unroll
    for (int o = 16; o > 0; o >>= 1) v = fmaxf(v, __shfl_xor_sync(0xffffffffu, v, o));
    return v;
}

static inline int divup(int a, int b) { return (a + b - 1) / b; }

// ------------------------------------------------------------------
// setup kernels (batched)
// ------------------------------------------------------------------
__global__ void k_zero_cnt() {
    int total = 3 * NN + NR;   // cnt_all, cnt_h, cnt_t, cnt_r are contiguous
    int* p = g_scr.cnt_all;
    for (int i = blockIdx.x * blockDim.x + threadIdx.x; i < total; i += gridDim.x * blockDim.x)
        p[i] = 0;
}

__global__ void k_hist4(const int* __restrict__ ii, const int* __restrict__ h,
                        const int* __restrict__ t, const int* __restrict__ rel) {
    int y = blockIdx.y;
    const int* keys; int n; int* cnt;
    if      (y == 0) { keys = ii;  n = NEA; cnt = g_scr.cnt_all; }
    else if (y == 1) { keys = h;   n = NE;  cnt = g_scr.cnt_h; }
    else if (y == 2) { keys = t;   n = NE;  cnt = g_scr.cnt_t; }
    else             { keys = rel; n = NE;  cnt = g_scr.cnt_r; }
    for (int i = blockIdx.x * blockDim.x + threadIdx.x; i < n; i += gridDim.x * blockDim.x)
        atomicAdd(&cnt[keys[i]], 1);
}

__global__ void k_scan_blk4() {
    int y = blockIdx.y;
    const int* c; int n; int* off;
    if      (y == 0) { c = g_scr.cnt_all; n = NN; off = g_scr.off_all; }
    else if (y == 1) { c = g_scr.cnt_h;   n = NN; off = g_scr.off_h; }
    else if (y == 2) { c = g_scr.cnt_t;   n = NN; off = g_scr.off_t; }
    else             { c = g_scr.cnt_r;   n = NR; off = g_scr.off_r; }
    if (blockIdx.x * 1024 >= n) return;
    __shared__ int sh[1024];
    int tid = threadIdx.x;
    int idx = blockIdx.x * 1024 + tid;
    int v = (idx < n) ? c[idx] : 0;
    sh[tid] = v;
    __syncthreads();
    #pragma unroll
    for (int d = 1; d < 1024; d <<= 1) {
        int t2 = (tid >= d) ? sh[tid - d] : 0;
        __syncthreads();
        sh[tid] += t2;
        __syncthreads();
    }
    if (idx < n) off[idx] = sh[tid] - v;
    if (tid == 1023) g_scr.bsum[y][blockIdx.x] = sh[1023];
}

__global__ void k_scan_top4() {
    if (threadIdx.x != 0 || blockIdx.x != 0) return;
    const int ns[4] = {NN, NN, NN, NR};
    int* endp[4] = {g_scr.off_all + NN, g_scr.off_h + NN, g_scr.off_t + NN, g_scr.off_r + NR};
    for (int y = 0; y < 4; y++) {
        int nb = (ns[y] + 1023) / 1024;
        int run = 0;
        for (int i = 0; i < nb; i++) { g_scr.boff[y][i] = run; run += g_scr.bsum[y][i]; }
        *endp[y] = run;
    }
}

__global__ void k_scan_fix4() {
    int y = blockIdx.y;
    int n; int* off; int* cur;
    if      (y == 0) { n = NN; off = g_scr.off_all; cur = g_scr.cur_all; }
    else if (y == 1) { n = NN; off = g_scr.off_h;   cur = g_scr.cur_h; }
    else if (y == 2) { n = NN; off = g_scr.off_t;   cur = g_scr.cur_t; }
    else             { n = NR; off = g_scr.off_r;   cur = g_scr.cur_r; }
    int idx = blockIdx.x * 1024 + threadIdx.x;
    if (idx < n) {
        int v = off[idx] + g_scr.boff[y][blockIdx.x];
        off[idx] = v;
        cur[idx] = v;
    }
}

__global__ void k_dinv() {
    int i = blockIdx.x * blockDim.x + threadIdx.x;
    if (i < NN) {
        int d = g_scr.cnt_all[i];
        g_scr.dinv[i] = (d > 0) ? rsqrtf((float)d) : 0.0f;
    }
}

// scatter values (not indices) into CSR order
__global__ void k_scatter4(const int* __restrict__ ii, const int* __restrict__ jjv,
                           const int* __restrict__ h, const int* __restrict__ t,
                           const int* __restrict__ rel) {
    int y = blockIdx.y;
    int stride = gridDim.x * blockDim.x;
    int i0 = blockIdx.x * blockDim.x + threadIdx.x;
    if (y == 0) {
        for (int i = i0; i < NEA; i += stride) {
            int pos = atomicAdd(&g_scr.cur_all[ii[i]], 1);
            int j = jjv[i];
            g_scr.jall[pos] = j;
            g_scr.wj[pos] = g_scr.dinv[j];
        }
    } else if (y == 1) {
        for (int i = i0; i < NE; i += stride) {
            int pos = atomicAdd(&g_scr.cur_h[h[i]], 1);
            g_scr.relh[pos] = rel[i];
        }
    } else if (y == 2) {
        for (int i = i0; i < NE; i += stride) {
            int pos = atomicAdd(&g_scr.cur_t[t[i]], 1);
            g_scr.relt[pos] = rel[i];
        }
    } else {
        for (int i = i0; i < NE; i += stride) {
            int pos = atomicAdd(&g_scr.cur_r[rel[i]], 1);
            g_scr.hr[pos] = h[i];
            g_scr.tr[pos] = t[i];
        }
    }
}

// ------------------------------------------------------------------
// GCN: warp per node, float4 gathers, presorted j/w
// ------------------------------------------------------------------
__global__ void k_gcn(const float* __restrict__ xin, float* __restrict__ yout) {
    int n = (blockIdx.x * blockDim.x + threadIdx.x) >> 5;
    if (n >= NN) return;
    int lane = threadIdx.x & 31;
    int s0 = g_scr.off_all[n], s1 = g_scr.off_all[n + 1];
    bool l2ok = (64 + lane) < 75;
    float4 a0 = {0,0,0,0}, a1 = {0,0,0,0}, a2 = {0,0,0,0};
    for (int p = s0; p < s1; p++) {
        int j = g_scr.jall[p];
        float w = g_scr.wj[p];
        const float4* xr = (const float4*)(xin + (size_t)j * EHD);
        float4 v0 = __ldg(xr + lane);
        float4 v1 = __ldg(xr + 32 + lane);
        a0.x += w*v0.x; a0.y += w*v0.y; a0.z += w*v0.z; a0.w += w*v0.w;
        a1.x += w*v1.x; a1.y += w*v1.y; a1.z += w*v1.z; a1.w += w*v1.w;
        if (l2ok) {
            float4 v2 = __ldg(xr + 64 + lane);
            a2.x += w*v2.x; a2.y += w*v2.y; a2.z += w*v2.z; a2.w += w*v2.w;
        }
    }
    float dn = g_scr.dinv[n];
    float4* yr = (float4*)(yout + (size_t)n * EHD);
    float4 o;
    o.x = fmaxf(dn*a0.x, 0.f); o.y = fmaxf(dn*a0.y, 0.f); o.z = fmaxf(dn*a0.z, 0.f); o.w = fmaxf(dn*a0.w, 0.f);
    yr[lane] = o;
    o.x = fmaxf(dn*a1.x, 0.f); o.y = fmaxf(dn*a1.y, 0.f); o.z = fmaxf(dn*a1.z, 0.f); o.w = fmaxf(dn*a1.w, 0.f);
    yr[32 + lane] = o;
    if (l2ok) {
        o.x = fmaxf(dn*a2.x, 0.f); o.y = fmaxf(dn*a2.y, 0.f); o.z = fmaxf(dn*a2.z, 0.f); o.w = fmaxf(dn*a2.w, 0.f);
        yr[64 + lane] = o;
    }
}

// ------------------------------------------------------------------
// bf16-split tensor-core GEMM, double-buffered with register prefetch
// ------------------------------------------------------------------
#define MMA_BF16(c, a, b) \
    asm volatile("mma.sync.aligned.m16n8k16.row.col.f32.bf16.bf16.f32 " \
        "{%0,%1,%2,%3}, {%4,%5,%6,%7}, {%8,%9}, {%0,%1,%2,%3};" \
        : "+f"((c)[0]), "+f"((c)[1]), "+f"((c)[2]), "+f"((c)[3]) \
        : "r"((a)[0]), "r"((a)[1]), "r"((a)[2]), "r"((a)[3]), \
          "r"((b)[0]), "r"((b)[1]))

#define LDSM_X4(r, p) \
    asm volatile("ldmatrix.sync.aligned.m8n8.x4.shared.b16 {%0,%1,%2,%3}, [%4];" \
        : "=r"((r)[0]), "=r"((r)[1]), "=r"((r)[2]), "=r"((r)[3]) : "r"(p))

#define LDSM_X2T(r, p) \
    asm volatile("ldmatrix.sync.aligned.m8n8.x2.trans.shared.b16 {%0,%1}, [%2];" \
        : "=r"((r)[0]), "=r"((r)[1]) : "r"(p))

#define AST 24
#define BST 72

__global__ __launch_bounds__(256) void k_hgemm(
    const float* __restrict__ A, const float* __restrict__ W,
    const float* __restrict__ bias, const float* __restrict__ Yp,
    float* __restrict__ OUT, int M, int N, int K, int mode) {
    __shared__ __nv_bfloat16 sAh[2][128 * AST];
    __shared__ __nv_bfloat16 sAl[2][128 * AST];
    __shared__ __nv_bfloat16 sBh[2][16 * BST];
    __shared__ __nv_bfloat16 sBl[2][16 * BST];

    const int mb = blockIdx.x * 128, nb = blockIdx.y * 64;
    const int tid = threadIdx.x;
    const int lane = tid & 31;
    const int wid = tid >> 5;
    const int warp_m = (wid & 3) * 32;
    const int warp_n = (wid >> 2) * 32;

    float acc[2][4][4];
    #pragma unroll
    for (int mt = 0; mt < 2; mt++)
        #pragma unroll
        for (int nt = 0; nt < 4; nt++)
            #pragma unroll
            for (int q = 0; q < 4; q++) acc[mt][nt][q] = 0.f;

    // ldmatrix lane pointers for buffer 0
    const int a_sub = lane >> 3;
    const int a_r   = lane & 7;
    const int a_row_off = ((a_sub & 1) << 3) + a_r;
    const int a_col     = (a_sub >> 1) << 3;
    uint32_t pAh0[2], pAl0[2];
    #pragma unroll
    for (int mt = 0; mt < 2; mt++) {
        int row = warp_m + mt * 16 + a_row_off;
        pAh0[mt] = (uint32_t)__cvta_generic_to_shared(&sAh[0][row * AST + a_col]);
        pAl0[mt] = (uint32_t)__cvta_generic_to_shared(&sAl[0][row * AST + a_col]);
    }
    const int b_row = lane & 15;
    uint32_t pBh0[4], pBl0[4];
    #pragma unroll
    for (int nt = 0; nt < 4; nt++) {
        int col = warp_n + nt * 8;
        pBh0[nt] = (uint32_t)__cvta_generic_to_shared(&sBh[0][b_row * BST + col]);
        pBl0[nt] = (uint32_t)__cvta_generic_to_shared(&sBl[0][b_row * BST + col]);
    }
    const uint32_t ABUF = (uint32_t)(128 * AST * 2);
    const uint32_t BBUF = (uint32_t)(16 * BST * 2);

    const int la_row = tid >> 1, la_cb = (tid & 1) * 8;
    const int lb_row = tid >> 4, lb_cb = (tid & 15) * 4;

    float ra[8], rb[4];
    auto load_tile = [&](int k0) {
        int gm = mb + la_row, c0 = k0 + la_cb;
        if (gm < M && c0 + 8 <= K) {
            const float4* p = (const float4*)(A + (size_t)gm * K + c0);
            float4 v0 = __ldg(p), v1 = __ldg(p + 1);
            ra[0]=v0.x; ra[1]=v0.y; ra[2]=v0.z; ra[3]=v0.w;
            ra[4]=v1.x; ra[5]=v1.y; ra[6]=v1.z; ra[7]=v1.w;
        } else {
            #pragma unroll
            for (int q = 0; q < 8; q++) {
                int gk = c0 + q;
                ra[q] = (gm < M && gk < K) ? A[(size_t)gm * K + gk] : 0.f;
            }
        }
        int gk = k0 + lb_row, cn = nb + lb_cb;
        if (gk < K && cn + 4 <= N) {
            float4 v = __ldg((const float4*)(W + (size_t)gk * N + cn));
            rb[0]=v.x; rb[1]=v.y; rb[2]=v.z; rb[3]=v.w;
        } else {
            #pragma unroll
            for (int q = 0; q < 4; q++) {
                int gn = cn + q;
                rb[q] = (gk < K && gn < N) ? W[(size_t)gk * N + gn] : 0.f;
            }
        }
    };
    auto store_tile = [&](int buf) {
        #pragma unroll
        for (int q = 0; q < 8; q++) {
            __nv_bfloat16 hi = __float2bfloat16(ra[q]);
            sAh[buf][la_row * AST + la_cb + q] = hi;
            sAl[buf][la_row * AST + la_cb + q] = __float2bfloat16(ra[q] - __bfloat162float(hi));
        }
        #pragma unroll
        for (int q = 0; q < 4; q++) {
            __nv_bfloat16 hi = __float2bfloat16(rb[q]);
            sBh[buf][lb_row * BST + lb_cb + q] = hi;
            sBl[buf][lb_row * BST + lb_cb + q] = __float2bfloat16(rb[q] - __bfloat162float(hi));
        }
    };

    int nk = (K + 15) / 16;
    load_tile(0);
    store_tile(0);
    __syncthreads();

    for (int ki = 0; ki < nk; ki++) {
        int buf = ki & 1;
        bool nxt = (ki + 1 < nk);
        if (nxt) load_tile((ki + 1) * 16);

        uint32_t aoff = buf * ABUF, boff = buf * BBUF;
        uint32_t ah[2][4], al[2][4], bh[4][2], bl[4][2];
        #pragma unroll
        for (int mt = 0; mt < 2; mt++) {
            LDSM_X4(ah[mt], pAh0[mt] + aoff);
            LDSM_X4(al[mt], pAl0[mt] + aoff);
        }
        #pragma unroll
        for (int nt = 0; nt < 4; nt++) {
            LDSM_X2T(bh[nt], pBh0[nt] + boff);
            LDSM_X2T(bl[nt], pBl0[nt] + boff);
        }
        #pragma unroll
        for (int mt = 0; mt < 2; mt++)
            #pragma unroll
            for (int nt = 0; nt < 4; nt++) {
                MMA_BF16(acc[mt][nt], ah[mt], bh[nt]);
                MMA_BF16(acc[mt][nt], ah[mt], bl[nt]);
                MMA_BF16(acc[mt][nt], al[mt], bh[nt]);
            }
        if (nxt) store_tile(buf ^ 1);
        __syncthreads();
    }

    const int erow = lane >> 2;
    const int ecol = (lane & 3) * 2;
    #pragma unroll
    for (int mt = 0; mt < 2; mt++) {
        #pragma unroll
        for (int nt = 0; nt < 4; nt++) {
            int r0 = mb + warp_m + mt * 16 + erow;
            int c0 = nb + warp_n + nt * 8 + ecol;
            #pragma unroll
            for (int q = 0; q < 4; q++) {
                int gm = r0 + (q >> 1) * 8;
                int gn = c0 + (q & 1);
                if (gm >= M || gn >= N) continue;
                float c = acc[mt][nt][q] + bias[gn];
                size_t o = (size_t)gm * N + gn;
                if (mode == 0) {
                    OUT[o] = c;
                } else {
                    float gg = 1.f / (1.f + expf(-c));
                    OUT[o] = gg * Yp[o] + (1.f - gg) * A[(size_t)gm * K + gn];
                }
            }
        }
    }
}

// ------------------------------------------------------------------
// per-relation means + rf2 + RF assembly (float4 gathers)
// ------------------------------------------------------------------
__global__ __launch_bounds__(256) void k_relmean(const float* __restrict__ sr1w,
                                                 const float* __restrict__ sr1b) {
    int r = blockIdx.x;
    int tid = threadIdx.x;
    __shared__ float acc[200];
    __shared__ float cat[200];
    if (tid < 200) acc[tid] = 0.f;
    __syncthreads();

    int wi = tid >> 5, lane = tid & 31;
    int s0 = g_scr.off_r[r], s1 = g_scr.off_r[r + 1];
    float4 lh = {0,0,0,0}, lt = {0,0,0,0};
    for (int p = s0 + wi; p < s1; p += 8) {
        int hh = g_scr.hr[p], tt = g_scr.tr[p];
        if (lane < 25) {
            const float4* sh_ = (const float4*)(g_scr.S + (size_t)hh * THD);
            const float4* st_ = (const float4*)(g_scr.S + (size_t)tt * THD);
            float4 v = __ldg(sh_ + lane);
            lh.x += v.x; lh.y += v.y; lh.z += v.z; lh.w += v.w;
            float4 u = __ldg(st_ + lane);
            lt.x += u.x; lt.y += u.y; lt.z += u.z; lt.w += u.w;
        }
    }
    if (lane < 25) {
        atomicAdd(&acc[4*lane+0], lh.x); atomicAdd(&acc[4*lane+1], lh.y);
        atomicAdd(&acc[4*lane+2], lh.z); atomicAdd(&acc[4*lane+3], lh.w);
        atomicAdd(&acc[100+4*lane+0], lt.x); atomicAdd(&acc[100+4*lane+1], lt.y);
        atomicAdd(&acc[100+4*lane+2], lt.z); atomicAdd(&acc[100+4*lane+3], lt.w);
    }
    __syncthreads();
    float c = fmaxf((float)g_scr.cnt_r[r], 1.f);
    if (tid < 200) cat[tid] = acc[tid] / c;
    __syncthreads();
    if (tid < 100) {
        float a = sr1b[tid];
        #pragma unroll 4
        for (int k = 0; k < 200; k++) a += cat[k] * sr1w[k * 100 + tid];
        float* rf = g_scr.RF + (size_t)r * EHD;
        rf[tid]       = a;
        rf[100 + tid] = cat[tid];
        rf[200 + tid] = cat[100 + tid];
    }
}

// ------------------------------------------------------------------
// batched small sgemm: ER_k = RF @ wr_k + br_k (blockIdx.z selects k)
// ------------------------------------------------------------------
__global__ __launch_bounds__(256) void k_sgemm3(
    const float* __restrict__ W0, const float* __restrict__ b0,
    const float* __restrict__ W1, const float* __restrict__ b1,
    const float* __restrict__ W2, const float* __restrict__ b2) {
    const float* W; const float* bias; float* OUT;
    int z = blockIdx.z;
    if      (z == 0) { W = W0; bias = b0; OUT = g_scr.ER0; }
    else if (z == 1) { W = W1; bias = b1; OUT = g_scr.ER1; }
    else             { W = W2; bias = b2; OUT = g_scr.ER2; }
    const float* A = g_scr.RF;
    const int M = NR, N = EHD, K = EHD;

    __shared__ float As[16][128];
    __shared__ float Bs[16][64];
    int mb = blockIdx.x * 128, nb = blockIdx.y * 64;
    int tid = threadIdx.x;
    int ty = tid >> 4;
    int tx = tid & 15;
    float acc[8][4];
    #pragma unroll
    for (int i = 0; i < 8; i++)
        #pragma unroll
        for (int j = 0; j < 4; j++) acc[i][j] = 0.f;

    for (int k0 = 0; k0 < K; k0 += 16) {
        #pragma unroll
        for (int l = 0; l < 8; l++) {
            int idx = tid + l * 256;
            int ar = idx >> 4, ak = idx & 15;
            int gm = mb + ar, gk = k0 + ak;
            As[ak][ar] = (gm < M && gk < K) ? A[(size_t)gm * K + gk] : 0.f;
        }
        #pragma unroll
        for (int l = 0; l < 4; l++) {
            int idx = tid + l * 256;
            int bn = idx & 63, bk = idx >> 6;
            int gk = k0 + bk, gn = nb + bn;
            Bs[bk][bn] = (gk < K && gn < N) ? W[(size_t)gk * N + gn] : 0.f;
        }
        __syncthreads();
        #pragma unroll
        for (int k = 0; k < 16; k++) {
            float a[8], b[4];
            #pragma unroll
            for (int i = 0; i < 8; i++) a[i] = As[k][ty * 8 + i];
            #pragma unroll
            for (int j = 0; j < 4; j++) b[j] = Bs[k][tx * 4 + j];
            #pragma unroll
            for (int i = 0; i < 8; i++)
                #pragma unroll
                for (int j = 0; j < 4; j++) acc[i][j] += a[i] * b[j];
        }
        __syncthreads();
    }
    #pragma unroll
    for (int i = 0; i < 8; i++) {
        int gm = mb + ty * 8 + i;
        if (gm >= M) continue;
        #pragma unroll
        for (int j = 0; j < 4; j++) {
            int gn = nb + tx * 4 + j;
            if (gn >= N) continue;
            OUT[(size_t)gm * N + gn] = acc[i][j] + bias[gn];
        }
    }
}

// ------------------------------------------------------------------
// batched rowdot over ER matrices: cR_k = ER_k . ar_k
// ------------------------------------------------------------------
__global__ void k_rowdot3(const float* __restrict__ v0, const float* __restrict__ v1,
                          const float* __restrict__ v2) {
    int y = blockIdx.y;
    const float* Mtx; const float* v; float* out;
    if      (y == 0) { Mtx = g_scr.ER0; v = v0; out = g_scr.cR0; }
    else if (y == 1) { Mtx = g_scr.ER1; v = v1; out = g_scr.cR1; }
    else             { Mtx = g_scr.ER2; v = v2; out = g_scr.cR2; }
    int r = (blockIdx.x * blockDim.x + threadIdx.x) >> 5;
    int lane = threadIdx.x & 31;
    if (r >= NR) return;
    const float4* mr = (const float4*)(Mtx + (size_t)r * EHD);
    const float4* vv = (const float4*)v;
    float s = 0.f;
    float4 a = mr[lane], b = vv[lane];
    s += a.x*b.x + a.y*b.y + a.z*b.z + a.w*b.w;
    a = mr[32 + lane]; b = vv[32 + lane];
    s += a.x*b.x + a.y*b.y + a.z*b.z + a.w*b.w;
    if (lane < 11) {
        a = mr[64 + lane]; b = vv[64 + lane];
        s += a.x*b.x + a.y*b.y + a.z*b.z + a.w*b.w;
    }
    s = wredsum(s);
    if (lane == 0) out[r] = s;
}

// ------------------------------------------------------------------
// rowdot over Z: xa = Z . v   (for the first attention round)
// ------------------------------------------------------------------
__global__ void k_rowdotZ(const float* __restrict__ v, float* __restrict__ out) {
    int n = (blockIdx.x * blockDim.x + threadIdx.x) >> 5;
    int lane = threadIdx.x & 31;
    if (n >= NN) return;
    const float4* mr = (const float4*)(g_scr.Z + (size_t)n * EHD);
    const float4* vv = (const float4*)v;
    float s = 0.f;
    float4 a = mr[lane], b = vv[lane];
    s += a.x*b.x + a.y*b.y + a.z*b.z + a.w*b.w;
    a = mr[32 + lane]; b = vv[32 + lane];
    s += a.x*b.x + a.y*b.y + a.z*b.z + a.w*b.w;
    if (lane < 11) {
        a = mr[64 + lane]; b = vv[64 + lane];
        s += a.x*b.x + a.y*b.y + a.z*b.z + a.w*b.w;
    }
    s = wredsum(s);
    if (lane == 0) out[n] = s;
}

// ------------------------------------------------------------------
// fused r2e: Z[n] += relu(softmax-agg of ER rows); then dot(s) with next
// attention vector(s), writing xa (and xj for the final round).
// ------------------------------------------------------------------
__global__ void k_r2e(const float* __restrict__ ER, const float* __restrict__ cR,
                      const int* __restrict__ off, const int* __restrict__ rels,
                      const float* __restrict__ an1, const float* __restrict__ an2,
                      float* __restrict__ xa1, float* __restrict__ xj2, int dual) {
    int n = (blockIdx.x * blockDim.x + threadIdx.x) >> 5;
    if (n >= NN) return;
    int lane = threadIdx.x & 31;
    int s0 = off[n], s1 = off[n + 1];
    bool l2ok = (64 + lane) < 75;
    float4 a0 = {0,0,0,0}, a1 = {0,0,0,0}, a2 = {0,0,0,0};

    if (s1 > s0) {
        float xan = g_scr.xa[n];
        float m = -1e30f;
        for (int p = s0 + lane; p < s1; p += 32)
            m = fmaxf(m, lrelu01(xan + cR[rels[p]]));
        m = wredmax(m);
        float den = 0.f;
        for (int p = s0 + lane; p < s1; p += 32)
            den += expf(lrelu01(xan + cR[rels[p]]) - m);
        den = wredsum(den);
        float inv = 1.f / den;
        for (int p = s0; p < s1; p++) {
            int r = rels[p];
            float w = expf(lrelu01(xan + cR[r]) - m) * inv;
            const float4* er = (const float4*)(ER + (size_t)r * EHD);
            float4 v0 = __ldg(er + lane);
            float4 v1 = __ldg(er + 32 + lane);
            a0.x += w*v0.x; a0.y += w*v0.y; a0.z += w*v0.z; a0.w += w*v0.w;
            a1.x += w*v1.x; a1.y += w*v1.y; a1.z += w*v1.z; a1.w += w*v1.w;
            if (l2ok) {
                float4 v2 = __ldg(er + 64 + lane);
                a2.x += w*v2.x; a2.y += w*v2.y; a2.z += w*v2.z; a2.w += w*v2.w;
            }
        }
    }
    // tail: update row, compute next-round dot(s)
    float4* xr = (float4*)(g_scr.Z + (size_t)n * EHD);
    const float4* w1 = (const float4*)an1;
    const float4* w2 = (const float4*)an2;
    float d1 = 0.f, d2 = 0.f;

    float4 v = xr[lane];
    v.x += fmaxf(a0.x, 0.f); v.y += fmaxf(a0.y, 0.f); v.z += fmaxf(a0.z, 0.f); v.w += fmaxf(a0.w, 0.f);
    xr[lane] = v;
    float4 q = w1[lane];
    d1 += v.x*q.x + v.y*q.y + v.z*q.z + v.w*q.w;
    if (dual) { float4 q2 = w2[lane]; d2 += v.x*q2.x + v.y*q2.y + v.z*q2.z + v.w*q2.w; }

    v = xr[32 + lane];
    v.x += fmaxf(a1.x, 0.f); v.y += fmaxf(a1.y, 0.f); v.z += fmaxf(a1.z, 0.f); v.w += fmaxf(a1.w, 0.f);
    xr[32 + lane] = v;
    q = w1[32 + lane];
    d1 += v.x*q.x + v.y*q.y + v.z*q.z + v.w*q.w;
    if (dual) { float4 q2 = w2[32 + lane]; d2 += v.x*q2.x + v.y*q2.y + v.z*q2.z + v.w*q2.w; }

    if (l2ok) {
        v = xr[64 + lane];
        v.x += fmaxf(a2.x, 0.f); v.y += fmaxf(a2.y, 0.f); v.z += fmaxf(a2.z, 0.f); v.w += fmaxf(a2.w, 0.f);
        xr[64 + lane] = v;
        q = w1[64 + lane];
        d1 += v.x*q.x + v.y*q.y + v.z*q.z + v.w*q.w;
        if (dual) { float4 q2 = w2[64 + lane]; d2 += v.x*q2.x + v.y*q2.y + v.z*q2.z + v.w*q2.w; }
    }
    d1 = wredsum(d1);
    if (lane == 0) xa1[n] = d1;
    if (dual) {
        d2 = wredsum(d2);
        if (lane == 0) xj2[n] = d2;
    }
}

// ------------------------------------------------------------------
// final GAT + fc output (float4, presorted j)
// ------------------------------------------------------------------
__global__ void k_gatfinal(const float* __restrict__ fcw, const float* __restrict__ fcb,
                           float* __restrict__ outp) {
    int n = (blockIdx.x * blockDim.x + threadIdx.x) >> 5;
    if (n >= NN) return;
    int lane = threadIdx.x & 31;
    int s0 = g_scr.off_all[n], s1 = g_scr.off_all[n + 1];
    bool l2ok = (64 + lane) < 75;
    float4 a0 = {0,0,0,0}, a1 = {0,0,0,0}, a2 = {0,0,0,0};

    if (s1 > s0) {
        float xin = g_scr.xa[n];
        float m = -1e30f;
        for (int p = s0 + lane; p < s1; p += 32)
            m = fmaxf(m, lrelu01(xin + g_scr.xj[g_scr.jall[p]]));
        m = wredmax(m);
        float den = 0.f;
        for (int p = s0 + lane; p < s1; p += 32)
            den += expf(lrelu01(xin + g_scr.xj[g_scr.jall[p]]) - m);
        den = wredsum(den);
        float inv = 1.f / den;
        for (int p = s0; p < s1; p++) {
            int j = g_scr.jall[p];
            float w = expf(lrelu01(xin + g_scr.xj[j]) - m) * inv;
            const float4* xr = (const float4*)(g_scr.Z + (size_t)j * EHD);
            float4 v0 = __ldg(xr + lane);
            float4 v1 = __ldg(xr + 32 + lane);
            a0.x += w*v0.x; a0.y += w*v0.y; a0.z += w*v0.z; a0.w += w*v0.w;
            a1.x += w*v1.x; a1.y += w*v1.y; a1.z += w*v1.z; a1.w += w*v1.w;
            if (l2ok) {
                float4 v2 = __ldg(xr + 64 + lane);
                a2.x += w*v2.x; a2.y += w*v2.y; a2.z += w*v2.z; a2.w += w*v2.w;
            }
        }
    }
    const float4* xn = (const float4*)(g_scr.Z + (size_t)n * EHD);
    const float4* f1 = (const float4*)fcw;
    const float4* f2 = (const float4*)(fcw + EHD);
    float local = 0.f;

    float4 v = xn[lane], q = f1[lane], g = f2[lane];
    local += v.x*q.x + v.y*q.y + v.z*q.z + v.w*q.w;
    local += fmaxf(a0.x,0.f)*g.x + fmaxf(a0.y,0.f)*g.y + fmaxf(a0.z,0.f)*g.z + fmaxf(a0.w,0.f)*g.w;
    v = xn[32+lane]; q = f1[32+lane]; g = f2[32+lane];
    local += v.x*q.x + v.y*q.y + v.z*q.z + v.w*q.w;
    local += fmaxf(a1.x,0.f)*g.x + fmaxf(a1.y,0.f)*g.y + fmaxf(a1.z,0.f)*g.z + fmaxf(a1.w,0.f)*g.w;
    if (l2ok) {
        v = xn[64+lane]; q = f1[64+lane]; g = f2[64+lane];
        local += v.x*q.x + v.y*q.y + v.z*q.z + v.w*q.w;
        local += fmaxf(a2.x,0.f)*g.x + fmaxf(a2.y,0.f)*g.y + fmaxf(a2.z,0.f)*g.z + fmaxf(a2.w,0.f)*g.w;
    }
    local = wredsum(local);
    if (lane == 0) outp[n] = local + fcb[0];
}

// ------------------------------------------------------------------
// launcher
// ------------------------------------------------------------------
extern "C" void kernel_launch(void* const* d_in, const int* in_sizes, int n_in,
                              void* d_out, int out_size) {
    const float* x      = (const float*)d_in[0];
    const int*   ei     = (const int*)d_in[1];
    const int*   rel    = (const int*)d_in[2];
    const int*   eia    = (const int*)d_in[3];
    const float* hw1_w  = (const float*)d_in[5];
    const float* hw1_b  = (const float*)d_in[6];
    const float* hw2_w  = (const float*)d_in[7];
    const float* hw2_b  = (const float*)d_in[8];
    const float* tc1_w  = (const float*)d_in[9];
    const float* tc1_b  = (const float*)d_in[10];
    const float* sr1_w  = (const float*)d_in[11];
    const float* sr1_b  = (const float*)d_in[12];
    const float* wr_w   = (const float*)d_in[15];
    const float* wr_b   = (const float*)d_in[16];
    const float* wr1_w  = (const float*)d_in[17];
    const float* wr1_b  = (const float*)d_in[18];
    const float* wr2_w  = (const float*)d_in[19];
    const float* wr2_b  = (const float*)d_in[20];
    const float* ah_w   = (const float*)d_in[21];
    const float* ah1_w  = (const float*)d_in[22];
    const float* at_w   = (const float*)d_in[23];
    const float* ar1_w  = (const float*)d_in[24];
    const float* ar2_w  = (const float*)d_in[25];
    const float* ar3_w  = (const float*)d_in[26];
    const float* ai_w   = (const float*)d_in[27];
    const float* aj_w   = (const float*)d_in[28];
    const float* fc_w   = (const float*)d_in[29];
    const float* fc_b   = (const float*)d_in[30];
    float* out = (float*)d_out;

    const int* h  = ei;
    const int* t  = ei + NE;
    const int* jj = eia;
    const int* ii = eia + NEA;

    Scratch* g = nullptr;
    cudaGetSymbolAddress((void**)&g, g_scr);

    const int TPB = 256;
    const int NODE_BLKS = divup(NN * 32, TPB);
    const int SCAN_BLKS = divup(NN, 1024);

    // ---- counting sorts --------------------------------------------------
    k_zero_cnt<<<128, TPB>>>();
    k_hist4<<<dim3(128, 4), TPB>>>(ii, h, t, rel);
    k_scan_blk4<<<dim3(SCAN_BLKS, 4), 1024>>>();
    k_scan_top4<<<1, 32>>>();
    k_scan_fix4<<<dim3(SCAN_BLKS, 4), 1024>>>();
    k_dinv<<<divup(NN, TPB), TPB>>>();
    k_scatter4<<<dim3(128, 4), TPB>>>(ii, jj, h, t, rel);

    // ---- highway GCN x2 + tc1 (tensor-core bf16-split GEMMs) -------------
    dim3 gemmGrid300(divup(NN, 128), divup(EHD, 64));
    dim3 gemmGrid100(divup(NN, 128), divup(THD, 64));
    k_gcn<<<NODE_BLKS, TPB>>>(x, g->Y);
    k_hgemm<<<gemmGrid300, 256>>>(x, hw1_w, hw1_b, g->Y, g->X, NN, EHD, EHD, 1);
    k_gcn<<<NODE_BLKS, TPB>>>(g->X, g->Y);
    k_hgemm<<<gemmGrid300, 256>>>(g->X, hw2_w, hw2_b, g->Y, g->Z, NN, EHD, EHD, 1);
    k_hgemm<<<gemmGrid100, 256>>>(g->Z, tc1_w, tc1_b, nullptr, g->S, NN, THD, EHD, 0);

    // ---- per-relation features + ER GEMMs + cR dots ----------------------
    k_relmean<<<NR, 256>>>(sr1_w, sr1_b);
    dim3 gemmGridR(divup(NR, 128), divup(EHD, 64), 3);
    k_sgemm3<<<gemmGridR, 256>>>(wr_w, wr_b, wr1_w, wr1_b, wr2_w, wr2_b);
    k_rowdot3<<<dim3(divup(NR * 32, TPB), 3), TPB>>>(ar1_w, ar2_w, ar3_w);

    // ---- three fused r2e rounds (h, t, h) --------------------------------
    k_rowdotZ<<<NODE_BLKS, TPB>>>(ah_w, g->xa);
    k_r2e<<<NODE_BLKS, TPB>>>(g->ER0, g->cR0, g->off_h, g->relh, at_w, nullptr, g->xa, nullptr, 0);
    k_r2e<<<NODE_BLKS, TPB>>>(g->ER1, g->cR1, g->off_t, g->relt, ah1_w, nullptr, g->xa, nullptr, 0);
    k_r2e<<<NODE_BLKS, TPB>>>(g->ER2, g->cR2, g->off_h, g->relh, ai_w, aj_w, g->xa, g->xj, 1);

    // ---- final GAT + fc ----------------------------------------------------
    k_gatfinal<<<NODE_BLKS, TPB>>>(fc_w, fc_b, out);
    (void)in_sizes; (void)n_in; (void)out_size;
}